// round 6
// baseline (speedup 1.0000x reference)
#include <cuda_runtime.h>
#include <cstdint>

#define Bv 4
#define Sv 4096
#define Hv 32
#define Dv 64
#define NSTEPS 128
#define ROWSTRIDE (Hv * Dv)       // 2048 floats between consecutive s
#define TILE 128                  // rows per tile (4 per warp)
#define NTILES (Sv / TILE)        // 32
#define TILE_FLOATS (TILE * Dv)   // 8192 floats = 32 KB
#define NBUF 3
#define FULL 0xffffffffu
#define PADP 35                   // conflict-free padding for s_ag rows

// sum across the 8 lanes of a row-group (lanes g*8..g*8+7)
__device__ __forceinline__ float grp8_sum(float v) {
    v += __shfl_xor_sync(FULL, v, 4);
    v += __shfl_xor_sync(FULL, v, 2);
    v += __shfl_xor_sync(FULL, v, 1);
    return v;
}

// inclusive scan across the 4 row-groups (stride-8 lanes)
__device__ __forceinline__ float scan_grp(float v, int lane) {
    float t = __shfl_up_sync(FULL, v, 8);
    if (lane >= 8) v += t;
    t = __shfl_up_sync(FULL, v, 16);
    if (lane >= 16) v += t;
    return v;
}

__device__ __forceinline__ float4 relu4(float4 a) {
    return make_float4(fmaxf(a.x, 0.f), fmaxf(a.y, 0.f),
                       fmaxf(a.z, 0.f), fmaxf(a.w, 0.f));
}
__device__ __forceinline__ float dot4(float4 a, float4 b) {
    return fmaf(a.x, b.x, fmaf(a.y, b.y, fmaf(a.z, b.z, a.w * b.w)));
}

__device__ __forceinline__ void cp16(float* dst_smem, const float* src) {
    uint32_t d = (uint32_t)__cvta_generic_to_shared(dst_smem);
    asm volatile("cp.async.cg.shared.global [%0], [%1], 16;"
                 :: "r"(d), "l"(src) : "memory");
}

__global__ __launch_bounds__(1024, 1)
void rope_ctx_kernel(const float* __restrict__ q,
                     const float* __restrict__ k,
                     const float* __restrict__ cos_step,
                     const float* __restrict__ sin_step,
                     float* __restrict__ out)
{
    extern __shared__ float smem[];
    float* sk = smem;                         // [NBUF][TILE][64]
    float* sq = smem + NBUF * TILE_FLOATS;    // [NBUF][TILE][64]

    __shared__ float2 s_tab[NSTEPS];
    // 3-parity aggregate/prefix array: A(t+1), C(t), E(t-1) use distinct slots
    __shared__ float  s_ag[3][64][PADP];

    const int tid  = threadIdx.x;
    const int w    = tid >> 5;
    const int lane = tid & 31;
    const int g    = lane >> 3;               // row group 0..3
    const int j    = lane & 7;                // dim slot within row
    const int b    = blockIdx.x >> 5;         // H = 32
    const int h    = blockIdx.x & 31;

    if (tid < NSTEPS) {
        s_tab[tid] = make_float2(cos_step[tid * Dv], sin_step[tid * Dv]);
    }

    const size_t base = (size_t)b * Sv * ROWSTRIDE + (size_t)h * Dv;
    const float* qg = q + base;
    const float* kg = k + base;
    float* og = out + base;
    const size_t KOUT = (size_t)Bv * Sv * ROWSTRIDE;

    const int dx = 4 * j;              // x dims: dx..dx+3 ; y dims: 32+dx..
    const int dy = 32 + 4 * j;
    const int r  = (w << 2) + g;       // this thread's row within a tile
    const int so = r << 6;             // thread's smem row base

    // per-thread-exact staging: a thread copies ONLY the words it will read
    auto issue = [&](int t) {
        if (t < NTILES) {
            const int p = t % NBUF;
            float* skb = sk + p * TILE_FLOATS;
            float* sqb = sq + p * TILE_FLOATS;
            const size_t go = (size_t)(t * TILE + r) * ROWSTRIDE;
            cp16(skb + so + dx, kg + go + dx);
            cp16(skb + so + dy, kg + go + dy);
            cp16(sqb + so + dx, qg + go + dx);
            cp16(sqb + so + dy, qg + go + dy);
        }
        asm volatile("cp.async.commit_group;" ::: "memory");
    };

    float4 basex = make_float4(0.f, 0.f, 0.f, 0.f);
    float4 basey = make_float4(0.f, 0.f, 0.f, 0.f);

    // A: load tile t (smem->reg), norms, local scan, publish warp aggregates
    auto phaseA = [&](int t, float4& ix, float4& iy, float& qinv) {
        const int p = t % NBUF, par = t % 3;
        const float* skb = sk + p * TILE_FLOATS;
        const float* sqb = sq + p * TILE_FLOATS;
        float4 kx = *(const float4*)(skb + so + dx);
        float4 ky = *(const float4*)(skb + so + dy);
        float4 qx = *(const float4*)(sqb + so + dx);
        float4 qy = *(const float4*)(sqb + so + dy);

        float4 knx = relu4(kx), kny = relu4(ky);
        float ss = grp8_sum(dot4(knx, knx) + dot4(kny, kny));
        float kinv = __fdividef(1.f, sqrtf(ss) + 1e-6f);
        knx.x *= kinv; knx.y *= kinv; knx.z *= kinv; knx.w *= kinv;
        kny.x *= kinv; kny.y *= kinv; kny.z *= kinv; kny.w *= kinv;

        ix.x = scan_grp(knx.x, lane); ix.y = scan_grp(knx.y, lane);
        ix.z = scan_grp(knx.z, lane); ix.w = scan_grp(knx.w, lane);
        iy.x = scan_grp(kny.x, lane); iy.y = scan_grp(kny.y, lane);
        iy.z = scan_grp(kny.z, lane); iy.w = scan_grp(kny.w, lane);

        if (g == 3) {                  // group 3 holds warp totals
            s_ag[par][dx    ][w] = ix.x; s_ag[par][dx + 1][w] = ix.y;
            s_ag[par][dx + 2][w] = ix.z; s_ag[par][dx + 3][w] = ix.w;
            s_ag[par][dy    ][w] = iy.x; s_ag[par][dy + 1][w] = iy.y;
            s_ag[par][dy + 2][w] = iy.z; s_ag[par][dy + 3][w] = iy.w;
        }

        float4 qrx = relu4(qx), qry = relu4(qy);
        float qs = grp8_sum(dot4(qrx, qrx) + dot4(qry, qry));
        qinv = __fdividef(1.f, sqrtf(qs) + 1e-6f);
    };

    // C: in-place cross-warp scan (warp w owns dims 2w,2w+1); writes shifted
    auto phaseC = [&](int t) {
        const int par = t % 3;
        #pragma unroll
        for (int dd = 0; dd < 2; ++dd) {
            const int d = 2 * w + dd;
            float v = s_ag[par][d][lane];
            float u;
            u = __shfl_up_sync(FULL, v, 1);  if (lane >= 1)  v += u;
            u = __shfl_up_sync(FULL, v, 2);  if (lane >= 2)  v += u;
            u = __shfl_up_sync(FULL, v, 4);  if (lane >= 4)  v += u;
            u = __shfl_up_sync(FULL, v, 8);  if (lane >= 8)  v += u;
            u = __shfl_up_sync(FULL, v, 16); if (lane >= 16) v += u;
            s_ag[par][d][lane + 1] = v;     // exclusive at [w], total at [32]
            if (lane == 0) s_ag[par][d][0] = 0.f;
        }
    };

    // E: reload k,q from smem buffer, assemble cum, dot, rope, store
    auto phaseE = [&](int t, const float4& ix, const float4& iy, float qinv) {
        const int p = t % NBUF, par = t % 3;
        const float* skb = sk + p * TILE_FLOATS;
        const float* sqb = sq + p * TILE_FLOATS;
        float4 kx = *(const float4*)(skb + so + dx);
        float4 ky = *(const float4*)(skb + so + dy);
        float4 qx = *(const float4*)(sqb + so + dx);
        float4 qy = *(const float4*)(sqb + so + dy);

        float4 cx, cy;
        cx.x = basex.x + s_ag[par][dx    ][w] + ix.x;
        cx.y = basex.y + s_ag[par][dx + 1][w] + ix.y;
        cx.z = basex.z + s_ag[par][dx + 2][w] + ix.z;
        cx.w = basex.w + s_ag[par][dx + 3][w] + ix.w;
        cy.x = basey.x + s_ag[par][dy    ][w] + iy.x;
        cy.y = basey.y + s_ag[par][dy + 1][w] + iy.y;
        cy.z = basey.z + s_ag[par][dy + 2][w] + iy.z;
        cy.w = basey.w + s_ag[par][dy + 3][w] + iy.w;

        basex.x += s_ag[par][dx    ][32]; basex.y += s_ag[par][dx + 1][32];
        basex.z += s_ag[par][dx + 2][32]; basex.w += s_ag[par][dx + 3][32];
        basey.x += s_ag[par][dy    ][32]; basey.y += s_ag[par][dy + 1][32];
        basey.z += s_ag[par][dy + 2][32]; basey.w += s_ag[par][dy + 3][32];

        float4 qrx = relu4(qx), qry = relu4(qy);
        float dot = grp8_sum(dot4(qrx, cx) + dot4(qry, cy)) * qinv;

        float pp = fminf(fmaxf(dot * (1.f / 32.f), 0.f), 127.f);
        float pf = floorf(pp);
        int   fi = (int)pf;
        int   ci = (int)ceilf(pp);
        float fr = pp - pf;
        float2 t0 = s_tab[fi], t1 = s_tab[ci];
        float cn = fmaf(fr, t1.x - t0.x, t0.x);
        float sn = fmaf(fr, t1.y - t0.y, t0.y);

        float4 oqx, oqy, okx, oky;
        oqx.x = fmaf(qx.x, cn, -qy.x * sn);  oqy.x = fmaf(qy.x, cn, qx.x * sn);
        oqx.y = fmaf(qx.y, cn, -qy.y * sn);  oqy.y = fmaf(qy.y, cn, qx.y * sn);
        oqx.z = fmaf(qx.z, cn, -qy.z * sn);  oqy.z = fmaf(qy.z, cn, qx.z * sn);
        oqx.w = fmaf(qx.w, cn, -qy.w * sn);  oqy.w = fmaf(qy.w, cn, qx.w * sn);
        okx.x = fmaf(kx.x, cn, -ky.x * sn);  oky.x = fmaf(ky.x, cn, kx.x * sn);
        okx.y = fmaf(kx.y, cn, -ky.y * sn);  oky.y = fmaf(ky.y, cn, kx.y * sn);
        okx.z = fmaf(kx.z, cn, -ky.z * sn);  oky.z = fmaf(ky.z, cn, kx.z * sn);
        okx.w = fmaf(kx.w, cn, -ky.w * sn);  oky.w = fmaf(ky.w, cn, kx.w * sn);

        const size_t ro = (size_t)(t * TILE + r) * ROWSTRIDE + dx;
        __stcs((float4*)(og + ro),             oqx);
        __stcs((float4*)(og + ro + 32),        oqy);
        __stcs((float4*)(og + KOUT + ro),      okx);
        __stcs((float4*)(og + KOUT + ro + 32), oky);
    };

    // ---- prologue ----------------------------------------------------------
    issue(0);
    issue(1);
    asm volatile("cp.async.wait_group 1;" ::: "memory");

    float4 ixA, iyA, ixB, iyB;
    float  qiA, qiB;
    phaseA(0, ixA, iyA, qiA);          // even tiles -> set A, odd -> set B

    // ---- main loop: ONE barrier per tile; unrolled x2 for static set idx ---
    for (int t = 0; t < NTILES; t += 2) {
        // interval t (even): C(t) | E(t-1,setB) | A(t+1)->setB
        __syncthreads();
        phaseC(t);
        if (t > 0) phaseE(t - 1, ixB, iyB, qiB);
        issue(t + 2);                          // after E's smem reads (WAR ok)
        asm volatile("cp.async.wait_group 1;" ::: "memory");
        phaseA(t + 1, ixB, iyB, qiB);

        // interval t+1 (odd): C(t+1) | E(t,setA) | A(t+2)->setA
        __syncthreads();
        phaseC(t + 1);
        phaseE(t, ixA, iyA, qiA);
        issue(t + 3);
        asm volatile("cp.async.wait_group 1;" ::: "memory");
        if (t + 2 < NTILES) phaseA(t + 2, ixA, iyA, qiA);
    }

    // ---- epilogue -----------------------------------------------------------
    __syncthreads();
    phaseE(NTILES - 1, ixB, iyB, qiB);
}

extern "C" void kernel_launch(void* const* d_in, const int* in_sizes, int n_in,
                              void* d_out, int out_size)
{
    const float* q        = (const float*)d_in[0];
    const float* k        = (const float*)d_in[1];
    // d_in[2] = v (unused by the reference math)
    const float* cos_step = (const float*)d_in[3];
    const float* sin_step = (const float*)d_in[4];
    // d_in[5] = offset (unused by the reference math)

    const size_t dyn = (size_t)2 * NBUF * TILE_FLOATS * sizeof(float); // 192 KB
    cudaFuncSetAttribute(rope_ctx_kernel,
                         cudaFuncAttributeMaxDynamicSharedMemorySize, (int)dyn);
    rope_ctx_kernel<<<Bv * Hv, 1024, dyn>>>(q, k, cos_step, sin_step,
                                            (float*)d_out);
}